// round 1
// baseline (speedup 1.0000x reference)
#include <cuda_runtime.h>
#include <math.h>

#define NNODES 50000
#define DIMC   128
#define DD     16
#define HH     8
#define HDD    16
#define SLOPEC 0.2f
#define ALPHAC 0.1f
#define LNEPS  1e-5f
// ln(17)/16
#define SCORE_SCALE 0.17707583400351351f

// Scratch: 9 buffers of N*128 floats + one N*512 buffer = N*1664 floats (~333MB)
__device__ float g_scratch[(size_t)NNODES * 1664];

// ---------------------------------------------------------------------------
// LayerNorm (optionally in+add, optionally store the pre-LN sum)
// One warp per row, float4 per lane.
// ---------------------------------------------------------------------------
__global__ void k_ln(const float* __restrict__ in, const float* __restrict__ add,
                     const float* __restrict__ g, const float* __restrict__ b,
                     float* __restrict__ out, float* __restrict__ sum_out, int n)
{
    int row  = blockIdx.x * 8 + (threadIdx.x >> 5);
    int lane = threadIdx.x & 31;
    if (row >= n) return;

    float4 v = ((const float4*)in)[(size_t)row * 32 + lane];
    if (add) {
        float4 w = ((const float4*)add)[(size_t)row * 32 + lane];
        v.x += w.x; v.y += w.y; v.z += w.z; v.w += w.w;
    }
    if (sum_out) ((float4*)sum_out)[(size_t)row * 32 + lane] = v;

    float s = v.x + v.y + v.z + v.w;
    #pragma unroll
    for (int o = 16; o; o >>= 1) s += __shfl_xor_sync(0xffffffffu, s, o);
    float mu = s * (1.0f / 128.0f);

    float dx = v.x - mu, dy = v.y - mu, dz = v.z - mu, dw = v.w - mu;
    float vs = dx * dx + dy * dy + dz * dz + dw * dw;
    #pragma unroll
    for (int o = 16; o; o >>= 1) vs += __shfl_xor_sync(0xffffffffu, vs, o);
    float rs = rsqrtf(vs * (1.0f / 128.0f) + LNEPS);

    float4 gg = ((const float4*)g)[lane];
    float4 bb = ((const float4*)b)[lane];
    float4 o4;
    o4.x = dx * rs * gg.x + bb.x;
    o4.y = dy * rs * gg.y + bb.y;
    o4.z = dz * rs * gg.z + bb.z;
    o4.w = dw * rs * gg.w + bb.w;
    ((float4*)out)[(size_t)row * 32 + lane] = o4;
}

// ---------------------------------------------------------------------------
// Tiled fp32 GEMM: C[M,Nc] = epilogue(A[M,K] @ B[K,Nc] + bias)
// 64x64 output tiles, K chunked by 64, 256 threads, 4x4 micro-tile.
// mode 0: plain  mode 1: relu  mode 2: + add[row,col]
// ---------------------------------------------------------------------------
__global__ void k_gemm(const float* __restrict__ A, const float* __restrict__ B,
                       const float* __restrict__ bias, const float* __restrict__ add,
                       float* __restrict__ C, int M, int K, int Nc, int mode)
{
    __shared__ float as[64][68];
    __shared__ float bs[64][68];

    int row0 = blockIdx.y * 64;
    int c0   = blockIdx.x * 64;
    int tid  = threadIdx.x;
    int ty   = tid >> 4;
    int tx   = tid & 15;

    float acc[4][4] = {};

    for (int k0 = 0; k0 < K; k0 += 64) {
        // load A tile (coalesced over k)
        #pragma unroll
        for (int i = tid; i < 64 * 64; i += 256) {
            int r  = i >> 6;
            int kk = i & 63;
            int node = row0 + r;
            as[r][kk] = (node < M) ? A[(size_t)node * K + k0 + kk] : 0.0f;
        }
        // load B tile (coalesced over c)
        #pragma unroll
        for (int i = tid; i < 64 * 64; i += 256) {
            int kk = i >> 6;
            int c  = i & 63;
            bs[kk][c] = B[(size_t)(k0 + kk) * Nc + c0 + c];
        }
        __syncthreads();

        #pragma unroll 8
        for (int kk = 0; kk < 64; ++kk) {
            float a0 = as[ty * 4 + 0][kk];
            float a1 = as[ty * 4 + 1][kk];
            float a2 = as[ty * 4 + 2][kk];
            float a3 = as[ty * 4 + 3][kk];
            float4 bv = *(const float4*)&bs[kk][tx * 4];
            acc[0][0] += a0 * bv.x; acc[0][1] += a0 * bv.y; acc[0][2] += a0 * bv.z; acc[0][3] += a0 * bv.w;
            acc[1][0] += a1 * bv.x; acc[1][1] += a1 * bv.y; acc[1][2] += a1 * bv.z; acc[1][3] += a1 * bv.w;
            acc[2][0] += a2 * bv.x; acc[2][1] += a2 * bv.y; acc[2][2] += a2 * bv.z; acc[2][3] += a2 * bv.w;
            acc[3][0] += a3 * bv.x; acc[3][1] += a3 * bv.y; acc[3][2] += a3 * bv.z; acc[3][3] += a3 * bv.w;
        }
        __syncthreads();
    }

    float4 bv = {0.f, 0.f, 0.f, 0.f};
    if (bias) bv = *(const float4*)&bias[c0 + tx * 4];

    #pragma unroll
    for (int i = 0; i < 4; ++i) {
        int node = row0 + ty * 4 + i;
        if (node >= M) continue;
        size_t base = (size_t)node * Nc + c0 + tx * 4;
        float4 r;
        r.x = acc[i][0] + bv.x;
        r.y = acc[i][1] + bv.y;
        r.z = acc[i][2] + bv.z;
        r.w = acc[i][3] + bv.w;
        if (mode == 1) {
            r.x = fmaxf(r.x, 0.f); r.y = fmaxf(r.y, 0.f);
            r.z = fmaxf(r.z, 0.f); r.w = fmaxf(r.w, 0.f);
        } else if (mode == 2) {
            float4 av = *(const float4*)&add[base];
            r.x += av.x; r.y += av.y; r.z += av.z; r.w += av.w;
        }
        *(float4*)&C[base] = r;
    }
}

// ---------------------------------------------------------------------------
// Attention: score -> softmax over D -> top-5 threshold -> normalized a_n
// One block (128 thr) per node. thread t -> (d = t/8, h = t%8)
// a_n stored as (N, H, D): n*128 + h*16 + d
// ---------------------------------------------------------------------------
__global__ void k_attn(const float* __restrict__ fh, const float* __restrict__ ft,
                       const float* __restrict__ attn, const int* __restrict__ src,
                       float* __restrict__ an, int n)
{
    int node = blockIdx.x;
    int tid  = threadIdx.x;
    __shared__ float fts[DIMC];
    __shared__ float ats[DIMC];
    __shared__ int   srcs[DD];
    __shared__ float sc[DD][HH];

    fts[tid] = ft[(size_t)node * DIMC + tid];
    ats[tid] = attn[tid];
    if (tid < DD) srcs[tid] = src[(size_t)node * DD + tid];
    __syncthreads();

    int d = tid >> 3;
    int h = tid & 7;
    const float* fr = fh + (size_t)srcs[d] * DIMC + h * HDD;
    const float* tr = fts + h * HDD;
    const float* ar = ats + h * HDD;
    float s = 0.f;
    #pragma unroll
    for (int f = 0; f < HDD; ++f) {
        float e = fr[f] + tr[f];
        e = (e >= 0.f) ? e : SLOPEC * e;
        s += e * ar[f];
    }
    sc[d][h] = s * SCORE_SCALE;
    __syncthreads();

    if (tid < HH) {
        int hh = tid;
        float a[DD];
        float m = -1e30f;
        #pragma unroll
        for (int dd = 0; dd < DD; ++dd) { a[dd] = sc[dd][hh]; m = fmaxf(m, a[dd]); }
        float sum = 0.f;
        #pragma unroll
        for (int dd = 0; dd < DD; ++dd) { a[dd] = expf(a[dd] - m); sum += a[dd]; }
        float inv = 1.f / sum;
        #pragma unroll
        for (int dd = 0; dd < DD; ++dd) a[dd] *= inv;

        // 5th-largest (counting duplicates) via 5-pass max removal
        float t[DD];
        #pragma unroll
        for (int dd = 0; dd < DD; ++dd) t[dd] = a[dd];
        float thr = 0.f;
        #pragma unroll
        for (int it = 0; it < 5; ++it) {
            float mx = -1.f; int mi = 0;
            #pragma unroll
            for (int dd = 0; dd < DD; ++dd)
                if (t[dd] > mx) { mx = t[dd]; mi = dd; }
            thr = mx;
            t[mi] = -1.f;
        }
        float ts = 0.f;
        #pragma unroll
        for (int dd = 0; dd < DD; ++dd)
            if (a[dd] >= thr) ts += a[dd];
        float itn = 1.f / ts;
        float* ao = an + (size_t)node * DIMC + hh * DD;
        #pragma unroll
        for (int dd = 0; dd < DD; ++dd)
            ao[dd] = (a[dd] >= thr) ? a[dd] * itn : 0.f;
    }
}

// ---------------------------------------------------------------------------
// One propagation hop: hout[n,h,f] = 0.9*sum_d a_n[n,h,d]*hin[src[n,d],h,f] + 0.1*fe[n,h,f]
// One block (128 thr) per node; thread t -> (h = t/16, f = t%16).
// Zero-weight neighbors are skipped (>=69% of entries are exactly 0).
// ---------------------------------------------------------------------------
__global__ void k_hop(const float* __restrict__ hin, const float* __restrict__ fe,
                      const float* __restrict__ an, const int* __restrict__ src,
                      float* __restrict__ hout, int n)
{
    int node = blockIdx.x;
    int tid  = threadIdx.x;
    __shared__ float coef[DIMC];
    __shared__ int   srcs[DD];
    coef[tid] = an[(size_t)node * DIMC + tid];
    if (tid < DD) srcs[tid] = src[(size_t)node * DD + tid];
    __syncthreads();

    int h = tid >> 4;
    float acc = 0.f;
    #pragma unroll
    for (int d = 0; d < DD; ++d) {
        float c = coef[h * DD + d];
        if (c != 0.f)
            acc += c * hin[(size_t)srcs[d] * DIMC + tid];
    }
    hout[(size_t)node * DIMC + tid] =
        (1.f - ALPHAC) * acc + ALPHAC * fe[(size_t)node * DIMC + tid];
}

// ---------------------------------------------------------------------------
extern "C" void kernel_launch(void* const* d_in, const int* in_sizes, int n_in,
                              void* d_out, int out_size)
{
    const float* feat   = (const float*)d_in[0];
    const float* W_head = (const float*)d_in[1];
    const float* W_tail = (const float*)d_in[2];
    const float* W_ent  = (const float*)d_in[3];
    const float* attn   = (const float*)d_in[4];
    const float* g1     = (const float*)d_in[5];
    const float* b1     = (const float*)d_in[6];
    const float* g2     = (const float*)d_in[7];
    const float* b2     = (const float*)d_in[8];
    const float* W_ff1  = (const float*)d_in[9];
    const float* b_ff1  = (const float*)d_in[10];
    const float* W_ff2  = (const float*)d_in[11];
    const float* b_ff2  = (const float*)d_in[12];
    const int*   src    = (const int*)d_in[13];
    float* out = (float*)d_out;

    int n = in_sizes[0] / DIMC;   // 50000
    if (n > NNODES) n = NNODES;

    float* scratch = nullptr;
    cudaGetSymbolAddress((void**)&scratch, g_scratch);
    const size_t SZ = (size_t)NNODES * DIMC;
    float* xln    = scratch + 0 * SZ;
    float* fh     = scratch + 1 * SZ;
    float* ft     = scratch + 2 * SZ;
    float* fe     = scratch + 3 * SZ;
    float* an     = scratch + 4 * SZ;
    float* h0     = scratch + 5 * SZ;
    float* h1     = scratch + 6 * SZ;
    float* rst    = scratch + 7 * SZ;
    float* y      = scratch + 8 * SZ;
    float* hidden = scratch + 9 * SZ;   // N * 512

    int lnGrid = (n + 7) / 8;
    int mTiles = (n + 63) / 64;

    // x = LN(feat)
    k_ln<<<lnGrid, 256>>>(feat, nullptr, g1, b1, xln, nullptr, n);

    // fh/ft/fe projections
    dim3 gp(2, mTiles);
    k_gemm<<<gp, 256>>>(xln, W_head, nullptr, nullptr, fh, n, 128, 128, 0);
    k_gemm<<<gp, 256>>>(xln, W_tail, nullptr, nullptr, ft, n, 128, 128, 0);
    k_gemm<<<gp, 256>>>(xln, W_ent,  nullptr, nullptr, fe, n, 128, 128, 0);

    // attention weights
    k_attn<<<n, 128>>>(fh, ft, attn, src, an, n);

    // 5 propagation hops (ping-pong)
    k_hop<<<n, 128>>>(fe, fe, an, src, h0, n);
    k_hop<<<n, 128>>>(h0, fe, an, src, h1, n);
    k_hop<<<n, 128>>>(h1, fe, an, src, h0, n);
    k_hop<<<n, 128>>>(h0, fe, an, src, h1, n);
    k_hop<<<n, 128>>>(h1, fe, an, src, h0, n);

    // rst = h + feat; y = LN(rst)
    k_ln<<<lnGrid, 256>>>(h0, feat, g2, b2, y, rst, n);

    // hidden = relu(y @ W_ff1 + b_ff1)
    dim3 gf1(8, mTiles);
    k_gemm<<<gf1, 256>>>(y, W_ff1, b_ff1, nullptr, hidden, n, 128, 512, 1);

    // out = hidden @ W_ff2 + b_ff2 + rst
    dim3 gf2(2, mTiles);
    k_gemm<<<gf2, 256>>>(hidden, W_ff2, b_ff2, rst, out, n, 512, 128, 2);
}

// round 2
// speedup vs baseline: 1.2180x; 1.2180x over previous
#include <cuda_runtime.h>
#include <math.h>
#include <stdint.h>

#define NNODES 50000
#define DIMC   128
#define DD     16
#define HH     8
#define HDD    16
#define SLOPEC 0.2f
#define ALPHAC 0.1f
#define LNEPS  1e-5f
// ln(17)/16
#define SCORE_SCALE 0.17707583400351351f

// Scratch: 9 buffers of N*128 floats + one N*512 buffer = N*1664 floats (~333MB)
__device__ float g_scratch[(size_t)NNODES * 1664];

// ---------------------------------------------------------------------------
// LayerNorm (optionally in+add, optionally store the pre-LN sum)
// ---------------------------------------------------------------------------
__global__ void k_ln(const float* __restrict__ in, const float* __restrict__ add,
                     const float* __restrict__ g, const float* __restrict__ b,
                     float* __restrict__ out, float* __restrict__ sum_out, int n)
{
    int row  = blockIdx.x * 8 + (threadIdx.x >> 5);
    int lane = threadIdx.x & 31;
    if (row >= n) return;

    float4 v = ((const float4*)in)[(size_t)row * 32 + lane];
    if (add) {
        float4 w = ((const float4*)add)[(size_t)row * 32 + lane];
        v.x += w.x; v.y += w.y; v.z += w.z; v.w += w.w;
    }
    if (sum_out) ((float4*)sum_out)[(size_t)row * 32 + lane] = v;

    float s = v.x + v.y + v.z + v.w;
    #pragma unroll
    for (int o = 16; o; o >>= 1) s += __shfl_xor_sync(0xffffffffu, s, o);
    float mu = s * (1.0f / 128.0f);

    float dx = v.x - mu, dy = v.y - mu, dz = v.z - mu, dw = v.w - mu;
    float vs = dx * dx + dy * dy + dz * dz + dw * dw;
    #pragma unroll
    for (int o = 16; o; o >>= 1) vs += __shfl_xor_sync(0xffffffffu, vs, o);
    float rs = rsqrtf(vs * (1.0f / 128.0f) + LNEPS);

    float4 gg = ((const float4*)g)[lane];
    float4 bb = ((const float4*)b)[lane];
    float4 o4;
    o4.x = dx * rs * gg.x + bb.x;
    o4.y = dy * rs * gg.y + bb.y;
    o4.z = dz * rs * gg.z + bb.z;
    o4.w = dw * rs * gg.w + bb.w;
    ((float4*)out)[(size_t)row * 32 + lane] = o4;
}

// ---------------------------------------------------------------------------
// 3xTF32 tensor-core GEMM: C[M,Nc] = epi(A[M,K] @ B[K,Nc] + bias)
// Block tile 128x64, BK=64, 256 threads (8 warps, 4x2), warp tile 32x32.
// A,B split into tf32 hi/lo at smem-fill; inner loop: 3 MMAs per pair.
// mode 0: plain  1: relu  2: + add[row,col]
// ---------------------------------------------------------------------------
#define A_STR 68
#define B_STR 72
#define SMEM_FLOATS (2*128*A_STR + 2*64*B_STR)

__device__ __forceinline__ uint32_t f2tf32(float v) {
    uint32_t r;
    asm("cvt.rna.tf32.f32 %0, %1;" : "=r"(r) : "f"(v));
    return r;
}

__device__ __forceinline__ void mma8(float* c, const uint32_t* a, const uint32_t* b) {
    asm volatile("mma.sync.aligned.m16n8k8.row.col.f32.tf32.tf32.f32 "
        "{%0,%1,%2,%3}, {%4,%5,%6,%7}, {%8,%9}, {%0,%1,%2,%3};\n"
        : "+f"(c[0]), "+f"(c[1]), "+f"(c[2]), "+f"(c[3])
        : "r"(a[0]), "r"(a[1]), "r"(a[2]), "r"(a[3]), "r"(b[0]), "r"(b[1]));
}

__global__ void __launch_bounds__(256)
k_gemm_tc(const float* __restrict__ A, const float* __restrict__ B,
          const float* __restrict__ bias, const float* __restrict__ add,
          float* __restrict__ C, int M, int K, int Nc, int mode)
{
    extern __shared__ float sm[];
    float* AsHi = sm;
    float* AsLo = AsHi + 128 * A_STR;
    float* BsHi = AsLo + 128 * A_STR;
    float* BsLo = BsHi + 64 * B_STR;

    int tid  = threadIdx.x;
    int warp = tid >> 5;
    int lane = tid & 31;
    int g    = lane >> 2;    // group id 0..7
    int tq   = lane & 3;     // thread in group 0..3

    int wm = warp >> 1;      // 0..3 : warp row block (32 rows each)
    int wn = warp & 1;       // 0..1 : warp col block (32 cols each)
    int wr = wm * 32;
    int wc = wn * 32;

    int row0 = blockIdx.y * 128;
    int c0   = blockIdx.x * 64;

    float acc[2][4][4] = {};

    for (int k0 = 0; k0 < K; k0 += 64) {
        // ---- fill A tiles (hi/lo split) : 128x64, float4 per slot ----
        #pragma unroll
        for (int s = 0; s < 8; ++s) {
            int slot = tid + s * 256;           // 0..2047
            int r  = slot >> 4;                 // 0..127
            int kk = (slot & 15) << 2;          // 0,4,..60
            int node = row0 + r;
            float4 v = {0.f, 0.f, 0.f, 0.f};
            if (node < M) v = *(const float4*)&A[(size_t)node * K + k0 + kk];
            float4 hi, lo;
            uint32_t h;
            h = f2tf32(v.x); hi.x = __uint_as_float(h); lo.x = __uint_as_float(f2tf32(v.x - hi.x));
            h = f2tf32(v.y); hi.y = __uint_as_float(h); lo.y = __uint_as_float(f2tf32(v.y - hi.y));
            h = f2tf32(v.z); hi.z = __uint_as_float(h); lo.z = __uint_as_float(f2tf32(v.z - hi.z));
            h = f2tf32(v.w); hi.w = __uint_as_float(h); lo.w = __uint_as_float(f2tf32(v.w - hi.w));
            *(float4*)&AsHi[r * A_STR + kk] = hi;
            *(float4*)&AsLo[r * A_STR + kk] = lo;
        }
        // ---- fill B tiles : 64x64 ----
        #pragma unroll
        for (int s = 0; s < 4; ++s) {
            int slot = tid + s * 256;           // 0..1023
            int kk = slot >> 4;                 // 0..63
            int cc = (slot & 15) << 2;          // 0..60
            float4 v = *(const float4*)&B[(size_t)(k0 + kk) * Nc + c0 + cc];
            float4 hi, lo;
            uint32_t h;
            h = f2tf32(v.x); hi.x = __uint_as_float(h); lo.x = __uint_as_float(f2tf32(v.x - hi.x));
            h = f2tf32(v.y); hi.y = __uint_as_float(h); lo.y = __uint_as_float(f2tf32(v.y - hi.y));
            h = f2tf32(v.z); hi.z = __uint_as_float(h); lo.z = __uint_as_float(f2tf32(v.z - hi.z));
            h = f2tf32(v.w); hi.w = __uint_as_float(h); lo.w = __uint_as_float(f2tf32(v.w - hi.w));
            *(float4*)&BsHi[kk * B_STR + cc] = hi;
            *(float4*)&BsLo[kk * B_STR + cc] = lo;
        }
        __syncthreads();

        // ---- inner MMA loop over 8 k-steps of 8 ----
        #pragma unroll
        for (int ks = 0; ks < 8; ++ks) {
            int k = ks * 8;
            uint32_t ahi[2][4], alo[2][4], bhi[4][2], blo[4][2];
            #pragma unroll
            for (int mf = 0; mf < 2; ++mf) {
                int r = wr + mf * 16 + g;
                ahi[mf][0] = __float_as_uint(AsHi[r * A_STR + k + tq]);
                ahi[mf][1] = __float_as_uint(AsHi[(r + 8) * A_STR + k + tq]);
                ahi[mf][2] = __float_as_uint(AsHi[r * A_STR + k + tq + 4]);
                ahi[mf][3] = __float_as_uint(AsHi[(r + 8) * A_STR + k + tq + 4]);
                alo[mf][0] = __float_as_uint(AsLo[r * A_STR + k + tq]);
                alo[mf][1] = __float_as_uint(AsLo[(r + 8) * A_STR + k + tq]);
                alo[mf][2] = __float_as_uint(AsLo[r * A_STR + k + tq + 4]);
                alo[mf][3] = __float_as_uint(AsLo[(r + 8) * A_STR + k + tq + 4]);
            }
            #pragma unroll
            for (int nf = 0; nf < 4; ++nf) {
                int c = wc + nf * 8 + g;
                bhi[nf][0] = __float_as_uint(BsHi[(k + tq) * B_STR + c]);
                bhi[nf][1] = __float_as_uint(BsHi[(k + tq + 4) * B_STR + c]);
                blo[nf][0] = __float_as_uint(BsLo[(k + tq) * B_STR + c]);
                blo[nf][1] = __float_as_uint(BsLo[(k + tq + 4) * B_STR + c]);
            }
            #pragma unroll
            for (int mf = 0; mf < 2; ++mf)
                #pragma unroll
                for (int nf = 0; nf < 4; ++nf) {
                    mma8(acc[mf][nf], ahi[mf], bhi[nf]);   // hi*hi
                    mma8(acc[mf][nf], ahi[mf], blo[nf]);   // hi*lo
                    mma8(acc[mf][nf], alo[mf], bhi[nf]);   // lo*hi
                }
        }
        __syncthreads();
    }

    // ---- epilogue ----
    #pragma unroll
    for (int mf = 0; mf < 2; ++mf) {
        #pragma unroll
        for (int nf = 0; nf < 4; ++nf) {
            int col = c0 + wc + nf * 8 + 2 * tq;
            float bx = 0.f, by = 0.f;
            if (bias) { bx = bias[col]; by = bias[col + 1]; }
            #pragma unroll
            for (int half = 0; half < 2; ++half) {
                int row = row0 + wr + mf * 16 + g + half * 8;
                if (row >= M) continue;
                float2 r;
                r.x = acc[mf][nf][half * 2 + 0] + bx;
                r.y = acc[mf][nf][half * 2 + 1] + by;
                size_t base = (size_t)row * Nc + col;
                if (mode == 1) {
                    r.x = fmaxf(r.x, 0.f); r.y = fmaxf(r.y, 0.f);
                } else if (mode == 2) {
                    float2 av = *(const float2*)&add[base];
                    r.x += av.x; r.y += av.y;
                }
                *(float2*)&C[base] = r;
            }
        }
    }
}

// ---------------------------------------------------------------------------
// Attention: score -> softmax over D -> top-5 threshold -> normalized a_n
// ---------------------------------------------------------------------------
__global__ void k_attn(const float* __restrict__ fh, const float* __restrict__ ft,
                       const float* __restrict__ attn, const int* __restrict__ src,
                       float* __restrict__ an, int n)
{
    int node = blockIdx.x;
    int tid  = threadIdx.x;
    __shared__ float fts[DIMC];
    __shared__ float ats[DIMC];
    __shared__ int   srcs[DD];
    __shared__ float sc[DD][HH];

    fts[tid] = ft[(size_t)node * DIMC + tid];
    ats[tid] = attn[tid];
    if (tid < DD) srcs[tid] = src[(size_t)node * DD + tid];
    __syncthreads();

    int d = tid >> 3;
    int h = tid & 7;
    const float* fr = fh + (size_t)srcs[d] * DIMC + h * HDD;
    const float* tr = fts + h * HDD;
    const float* ar = ats + h * HDD;
    float s = 0.f;
    #pragma unroll
    for (int f = 0; f < HDD; ++f) {
        float e = fr[f] + tr[f];
        e = (e >= 0.f) ? e : SLOPEC * e;
        s += e * ar[f];
    }
    sc[d][h] = s * SCORE_SCALE;
    __syncthreads();

    if (tid < HH) {
        int hh = tid;
        float a[DD];
        float m = -1e30f;
        #pragma unroll
        for (int dd = 0; dd < DD; ++dd) { a[dd] = sc[dd][hh]; m = fmaxf(m, a[dd]); }
        float sum = 0.f;
        #pragma unroll
        for (int dd = 0; dd < DD; ++dd) { a[dd] = expf(a[dd] - m); sum += a[dd]; }
        float inv = 1.f / sum;
        #pragma unroll
        for (int dd = 0; dd < DD; ++dd) a[dd] *= inv;

        float t[DD];
        #pragma unroll
        for (int dd = 0; dd < DD; ++dd) t[dd] = a[dd];
        float thr = 0.f;
        #pragma unroll
        for (int it = 0; it < 5; ++it) {
            float mx = -1.f; int mi = 0;
            #pragma unroll
            for (int dd = 0; dd < DD; ++dd)
                if (t[dd] > mx) { mx = t[dd]; mi = dd; }
            thr = mx;
            t[mi] = -1.f;
        }
        float ts = 0.f;
        #pragma unroll
        for (int dd = 0; dd < DD; ++dd)
            if (a[dd] >= thr) ts += a[dd];
        float itn = 1.f / ts;
        float* ao = an + (size_t)node * DIMC + hh * DD;
        #pragma unroll
        for (int dd = 0; dd < DD; ++dd)
            ao[dd] = (a[dd] >= thr) ? a[dd] * itn : 0.f;
    }
}

// ---------------------------------------------------------------------------
// One propagation hop
// ---------------------------------------------------------------------------
__global__ void k_hop(const float* __restrict__ hin, const float* __restrict__ fe,
                      const float* __restrict__ an, const int* __restrict__ src,
                      float* __restrict__ hout, int n)
{
    int node = blockIdx.x;
    int tid  = threadIdx.x;
    __shared__ float coef[DIMC];
    __shared__ int   srcs[DD];
    coef[tid] = an[(size_t)node * DIMC + tid];
    if (tid < DD) srcs[tid] = src[(size_t)node * DD + tid];
    __syncthreads();

    int h = tid >> 4;
    float acc = 0.f;
    #pragma unroll
    for (int d = 0; d < DD; ++d) {
        float c = coef[h * DD + d];
        if (c != 0.f)
            acc += c * hin[(size_t)srcs[d] * DIMC + tid];
    }
    hout[(size_t)node * DIMC + tid] =
        (1.f - ALPHAC) * acc + ALPHAC * fe[(size_t)node * DIMC + tid];
}

// ---------------------------------------------------------------------------
extern "C" void kernel_launch(void* const* d_in, const int* in_sizes, int n_in,
                              void* d_out, int out_size)
{
    const float* feat   = (const float*)d_in[0];
    const float* W_head = (const float*)d_in[1];
    const float* W_tail = (const float*)d_in[2];
    const float* W_ent  = (const float*)d_in[3];
    const float* attn   = (const float*)d_in[4];
    const float* g1     = (const float*)d_in[5];
    const float* b1     = (const float*)d_in[6];
    const float* g2     = (const float*)d_in[7];
    const float* b2     = (const float*)d_in[8];
    const float* W_ff1  = (const float*)d_in[9];
    const float* b_ff1  = (const float*)d_in[10];
    const float* W_ff2  = (const float*)d_in[11];
    const float* b_ff2  = (const float*)d_in[12];
    const int*   src    = (const int*)d_in[13];
    float* out = (float*)d_out;

    int n = in_sizes[0] / DIMC;   // 50000
    if (n > NNODES) n = NNODES;

    float* scratch = nullptr;
    cudaGetSymbolAddress((void**)&scratch, g_scratch);
    const size_t SZ = (size_t)NNODES * DIMC;
    float* xln    = scratch + 0 * SZ;
    float* fh     = scratch + 1 * SZ;
    float* ft     = scratch + 2 * SZ;
    float* fe     = scratch + 3 * SZ;
    float* an     = scratch + 4 * SZ;
    float* h0     = scratch + 5 * SZ;
    float* h1     = scratch + 6 * SZ;
    float* rst    = scratch + 7 * SZ;
    float* y      = scratch + 8 * SZ;
    float* hidden = scratch + 9 * SZ;   // N * 512

    const int SMEM_BYTES = SMEM_FLOATS * 4;
    cudaFuncSetAttribute(k_gemm_tc, cudaFuncAttributeMaxDynamicSharedMemorySize, SMEM_BYTES);

    int lnGrid = (n + 7) / 8;
    int mTiles = (n + 127) / 128;

    // x = LN(feat)
    k_ln<<<lnGrid, 256>>>(feat, nullptr, g1, b1, xln, nullptr, n);

    // fh/ft/fe projections (tensor cores, 3xTF32)
    dim3 gp(2, mTiles);
    k_gemm_tc<<<gp, 256, SMEM_BYTES>>>(xln, W_head, nullptr, nullptr, fh, n, 128, 128, 0);
    k_gemm_tc<<<gp, 256, SMEM_BYTES>>>(xln, W_tail, nullptr, nullptr, ft, n, 128, 128, 0);
    k_gemm_tc<<<gp, 256, SMEM_BYTES>>>(xln, W_ent,  nullptr, nullptr, fe, n, 128, 128, 0);

    // attention weights
    k_attn<<<n, 128>>>(fh, ft, attn, src, an, n);

    // 5 propagation hops (ping-pong)
    k_hop<<<n, 128>>>(fe, fe, an, src, h0, n);
    k_hop<<<n, 128>>>(h0, fe, an, src, h1, n);
    k_hop<<<n, 128>>>(h1, fe, an, src, h0, n);
    k_hop<<<n, 128>>>(h0, fe, an, src, h1, n);
    k_hop<<<n, 128>>>(h1, fe, an, src, h0, n);

    // rst = h + feat; y = LN(rst)
    k_ln<<<lnGrid, 256>>>(h0, feat, g2, b2, y, rst, n);

    // hidden = relu(y @ W_ff1 + b_ff1)
    dim3 gf1(8, mTiles);
    k_gemm_tc<<<gf1, 256, SMEM_BYTES>>>(y, W_ff1, b_ff1, nullptr, hidden, n, 128, 512, 1);

    // out = hidden @ W_ff2 + b_ff2 + rst
    dim3 gf2(2, mTiles);
    k_gemm_tc<<<gf2, 256, SMEM_BYTES>>>(hidden, W_ff2, b_ff2, rst, out, n, 512, 128, 2);
}

// round 3
// speedup vs baseline: 1.6844x; 1.3829x over previous
#include <cuda_runtime.h>
#include <math.h>
#include <stdint.h>

#define NNODES 50000
#define DIMC   128
#define DD     16
#define HH     8
#define HDD    16
#define SLOPEC 0.2f
#define ALPHAC 0.1f
#define LNEPS  1e-5f
// ln(17)/16
#define SCORE_SCALE 0.17707583400351351f

// Scratch: 15 buffers of N*128 floats (~384MB)
__device__ float g_scratch[(size_t)NNODES * 1920];

// ---------------------------------------------------------------------------
// LayerNorm (optionally in+add, optionally store the pre-LN sum)
// ---------------------------------------------------------------------------
__global__ void k_ln(const float* __restrict__ in, const float* __restrict__ add,
                     const float* __restrict__ g, const float* __restrict__ b,
                     float* __restrict__ out, float* __restrict__ sum_out, int n)
{
    int row  = blockIdx.x * 8 + (threadIdx.x >> 5);
    int lane = threadIdx.x & 31;
    if (row >= n) return;

    float4 v = ((const float4*)in)[(size_t)row * 32 + lane];
    if (add) {
        float4 w = ((const float4*)add)[(size_t)row * 32 + lane];
        v.x += w.x; v.y += w.y; v.z += w.z; v.w += w.w;
    }
    if (sum_out) ((float4*)sum_out)[(size_t)row * 32 + lane] = v;

    float s = v.x + v.y + v.z + v.w;
    #pragma unroll
    for (int o = 16; o; o >>= 1) s += __shfl_xor_sync(0xffffffffu, s, o);
    float mu = s * (1.0f / 128.0f);

    float dx = v.x - mu, dy = v.y - mu, dz = v.z - mu, dw = v.w - mu;
    float vs = dx * dx + dy * dy + dz * dz + dw * dw;
    #pragma unroll
    for (int o = 16; o; o >>= 1) vs += __shfl_xor_sync(0xffffffffu, vs, o);
    float rs = rsqrtf(vs * (1.0f / 128.0f) + LNEPS);

    float4 gg = ((const float4*)g)[lane];
    float4 bb = ((const float4*)b)[lane];
    float4 o4;
    o4.x = dx * rs * gg.x + bb.x;
    o4.y = dy * rs * gg.y + bb.y;
    o4.z = dz * rs * gg.z + bb.z;
    o4.w = dw * rs * gg.w + bb.w;
    ((float4*)out)[(size_t)row * 32 + lane] = o4;
}

// ---------------------------------------------------------------------------
// 3xTF32 tensor-core GEMM: block 128x128, BK=64, 8 warps (4x2), warp 32x64.
// 1 LDS per MMA. mode 0: plain  1: relu  2: + add[row,col]
// ---------------------------------------------------------------------------
#define A_STR 68
#define B_STR 136
#define SMEM_FLOATS (2*128*A_STR + 2*64*B_STR)

__device__ __forceinline__ uint32_t f2tf32(float v) {
    uint32_t r;
    asm("cvt.rna.tf32.f32 %0, %1;" : "=r"(r) : "f"(v));
    return r;
}

__device__ __forceinline__ void mma8(float* c, const uint32_t* a, const uint32_t* b) {
    asm volatile("mma.sync.aligned.m16n8k8.row.col.f32.tf32.tf32.f32 "
        "{%0,%1,%2,%3}, {%4,%5,%6,%7}, {%8,%9}, {%0,%1,%2,%3};\n"
        : "+f"(c[0]), "+f"(c[1]), "+f"(c[2]), "+f"(c[3])
        : "r"(a[0]), "r"(a[1]), "r"(a[2]), "r"(a[3]), "r"(b[0]), "r"(b[1]));
}

__global__ void __launch_bounds__(256)
k_gemm_tc(const float* __restrict__ A, const float* __restrict__ B,
          const float* __restrict__ bias, const float* __restrict__ add,
          float* __restrict__ C, int M, int K, int Nc, int mode)
{
    extern __shared__ float sm[];
    float* AsHi = sm;
    float* AsLo = AsHi + 128 * A_STR;
    float* BsHi = AsLo + 128 * A_STR;
    float* BsLo = BsHi + 64 * B_STR;

    int tid  = threadIdx.x;
    int warp = tid >> 5;
    int lane = tid & 31;
    int g    = lane >> 2;    // 0..7
    int tq   = lane & 3;     // 0..3

    int wr = (warp >> 1) * 32;   // warp row offset 0/32/64/96
    int wc = (warp & 1) * 64;    // warp col offset 0/64

    int row0 = blockIdx.y * 128;
    int c0   = blockIdx.x * 128;

    float acc[2][8][4] = {};

    for (int k0 = 0; k0 < K; k0 += 64) {
        // ---- fill A tile 128x64 (hi/lo split) ----
        #pragma unroll
        for (int s = 0; s < 8; ++s) {
            int slot = tid + s * 256;            // 0..2047
            int r  = slot >> 4;
            int kk = (slot & 15) << 2;
            int node = row0 + r;
            float4 v = {0.f, 0.f, 0.f, 0.f};
            if (node < M) v = *(const float4*)&A[(size_t)node * K + k0 + kk];
            float4 hi, lo;
            uint32_t h;
            h = f2tf32(v.x); hi.x = __uint_as_float(h); lo.x = __uint_as_float(f2tf32(v.x - hi.x));
            h = f2tf32(v.y); hi.y = __uint_as_float(h); lo.y = __uint_as_float(f2tf32(v.y - hi.y));
            h = f2tf32(v.z); hi.z = __uint_as_float(h); lo.z = __uint_as_float(f2tf32(v.z - hi.z));
            h = f2tf32(v.w); hi.w = __uint_as_float(h); lo.w = __uint_as_float(f2tf32(v.w - hi.w));
            *(float4*)&AsHi[r * A_STR + kk] = hi;
            *(float4*)&AsLo[r * A_STR + kk] = lo;
        }
        // ---- fill B tile 64x128 ----
        #pragma unroll
        for (int s = 0; s < 8; ++s) {
            int slot = tid + s * 256;            // 0..2047
            int kk = slot >> 5;                  // 0..63
            int cc = (slot & 31) << 2;           // 0..124
            float4 v = *(const float4*)&B[(size_t)(k0 + kk) * Nc + c0 + cc];
            float4 hi, lo;
            uint32_t h;
            h = f2tf32(v.x); hi.x = __uint_as_float(h); lo.x = __uint_as_float(f2tf32(v.x - hi.x));
            h = f2tf32(v.y); hi.y = __uint_as_float(h); lo.y = __uint_as_float(f2tf32(v.y - hi.y));
            h = f2tf32(v.z); hi.z = __uint_as_float(h); lo.z = __uint_as_float(f2tf32(v.z - hi.z));
            h = f2tf32(v.w); hi.w = __uint_as_float(h); lo.w = __uint_as_float(f2tf32(v.w - hi.w));
            *(float4*)&BsHi[kk * B_STR + cc] = hi;
            *(float4*)&BsLo[kk * B_STR + cc] = lo;
        }
        __syncthreads();

        #pragma unroll
        for (int ks = 0; ks < 8; ++ks) {
            int k = ks * 8;
            uint32_t ahi[2][4], alo[2][4], bhi[8][2], blo[8][2];
            #pragma unroll
            for (int mf = 0; mf < 2; ++mf) {
                int r = wr + mf * 16 + g;
                ahi[mf][0] = __float_as_uint(AsHi[r * A_STR + k + tq]);
                ahi[mf][1] = __float_as_uint(AsHi[(r + 8) * A_STR + k + tq]);
                ahi[mf][2] = __float_as_uint(AsHi[r * A_STR + k + tq + 4]);
                ahi[mf][3] = __float_as_uint(AsHi[(r + 8) * A_STR + k + tq + 4]);
                alo[mf][0] = __float_as_uint(AsLo[r * A_STR + k + tq]);
                alo[mf][1] = __float_as_uint(AsLo[(r + 8) * A_STR + k + tq]);
                alo[mf][2] = __float_as_uint(AsLo[r * A_STR + k + tq + 4]);
                alo[mf][3] = __float_as_uint(AsLo[(r + 8) * A_STR + k + tq + 4]);
            }
            #pragma unroll
            for (int nf = 0; nf < 8; ++nf) {
                int c = wc + nf * 8 + g;
                bhi[nf][0] = __float_as_uint(BsHi[(k + tq) * B_STR + c]);
                bhi[nf][1] = __float_as_uint(BsHi[(k + tq + 4) * B_STR + c]);
                blo[nf][0] = __float_as_uint(BsLo[(k + tq) * B_STR + c]);
                blo[nf][1] = __float_as_uint(BsLo[(k + tq + 4) * B_STR + c]);
            }
            #pragma unroll
            for (int mf = 0; mf < 2; ++mf)
                #pragma unroll
                for (int nf = 0; nf < 8; ++nf) {
                    mma8(acc[mf][nf], ahi[mf], bhi[nf]);
                    mma8(acc[mf][nf], ahi[mf], blo[nf]);
                    mma8(acc[mf][nf], alo[mf], bhi[nf]);
                }
        }
        __syncthreads();
    }

    // ---- epilogue ----
    #pragma unroll
    for (int mf = 0; mf < 2; ++mf) {
        #pragma unroll
        for (int nf = 0; nf < 8; ++nf) {
            int col = c0 + wc + nf * 8 + 2 * tq;
            float bx = 0.f, by = 0.f;
            if (bias) { bx = bias[col]; by = bias[col + 1]; }
            #pragma unroll
            for (int half = 0; half < 2; ++half) {
                int row = row0 + wr + mf * 16 + g + half * 8;
                if (row >= M) continue;
                float2 r;
                r.x = acc[mf][nf][half * 2 + 0] + bx;
                r.y = acc[mf][nf][half * 2 + 1] + by;
                size_t base = (size_t)row * Nc + col;
                if (mode == 1) {
                    r.x = fmaxf(r.x, 0.f); r.y = fmaxf(r.y, 0.f);
                } else if (mode == 2) {
                    float2 av = *(const float2*)&add[base];
                    r.x += av.x; r.y += av.y;
                }
                *(float2*)&C[base] = r;
            }
        }
    }
}

// ---------------------------------------------------------------------------
// Attention: score -> softmax -> top-5 threshold -> COMPACT normalized lists
// Emits per (node,head): cnt entries of (weight, gathered src node id).
// ---------------------------------------------------------------------------
__global__ void k_attn(const float* __restrict__ fh, const float* __restrict__ ft,
                       const float* __restrict__ attn, const int* __restrict__ src,
                       float* __restrict__ wcmp, int* __restrict__ scmp,
                       int* __restrict__ cnt, int n)
{
    int node = blockIdx.x;
    int tid  = threadIdx.x;
    __shared__ __align__(16) float fts[DIMC];
    __shared__ __align__(16) float ats[DIMC];
    __shared__ int   srcs[DD];
    __shared__ float sc[DD][HH];

    fts[tid] = ft[(size_t)node * DIMC + tid];
    ats[tid] = attn[tid];
    if (tid < DD) srcs[tid] = src[(size_t)node * DD + tid];
    __syncthreads();

    int d = tid >> 3;
    int h = tid & 7;
    const float4* fr = (const float4*)(fh + (size_t)srcs[d] * DIMC + h * HDD);
    const float4* tr = (const float4*)(fts + h * HDD);
    const float4* ar = (const float4*)(ats + h * HDD);
    float s = 0.f;
    #pragma unroll
    for (int f = 0; f < 4; ++f) {
        float4 fv = fr[f], tv = tr[f], av = ar[f];
        float e;
        e = fv.x + tv.x; e = (e >= 0.f) ? e : SLOPEC * e; s += e * av.x;
        e = fv.y + tv.y; e = (e >= 0.f) ? e : SLOPEC * e; s += e * av.y;
        e = fv.z + tv.z; e = (e >= 0.f) ? e : SLOPEC * e; s += e * av.z;
        e = fv.w + tv.w; e = (e >= 0.f) ? e : SLOPEC * e; s += e * av.w;
    }
    sc[d][h] = s * SCORE_SCALE;
    __syncthreads();

    if (tid < HH) {
        int hh = tid;
        float a[DD];
        float m = -1e30f;
        #pragma unroll
        for (int dd = 0; dd < DD; ++dd) { a[dd] = sc[dd][hh]; m = fmaxf(m, a[dd]); }
        float sum = 0.f;
        #pragma unroll
        for (int dd = 0; dd < DD; ++dd) { a[dd] = expf(a[dd] - m); sum += a[dd]; }
        float inv = 1.f / sum;
        #pragma unroll
        for (int dd = 0; dd < DD; ++dd) a[dd] *= inv;

        // 5th-largest (counting duplicates) via 5-pass max removal
        float t[DD];
        #pragma unroll
        for (int dd = 0; dd < DD; ++dd) t[dd] = a[dd];
        float thr = 0.f;
        #pragma unroll
        for (int it = 0; it < 5; ++it) {
            float mx = -1.f; int mi = 0;
            #pragma unroll
            for (int dd = 0; dd < DD; ++dd)
                if (t[dd] > mx) { mx = t[dd]; mi = dd; }
            thr = mx;
            t[mi] = -1.f;
        }
        float ts = 0.f;
        #pragma unroll
        for (int dd = 0; dd < DD; ++dd)
            if (a[dd] >= thr) ts += a[dd];
        float itn = 1.f / ts;

        size_t base = ((size_t)node * HH + hh) * 16;
        int c = 0;
        #pragma unroll
        for (int dd = 0; dd < DD; ++dd) {
            if (a[dd] >= thr) {
                wcmp[base + c] = a[dd] * itn;
                scmp[base + c] = srcs[dd];
                ++c;
            }
        }
        cnt[(size_t)node * HH + hh] = c;
    }
}

// ---------------------------------------------------------------------------
// One propagation hop using compact lists. One warp per node.
// lane -> (h = lane/4, q = lane%4): float4 over 16 feats of head h.
// ---------------------------------------------------------------------------
__global__ void k_hop(const float* __restrict__ hin, const float* __restrict__ fe,
                      const float* __restrict__ wcmp, const int* __restrict__ scmp,
                      const int* __restrict__ cnt, float* __restrict__ hout, int n)
{
    int node = blockIdx.x * 8 + (threadIdx.x >> 5);
    if (node >= n) return;
    int lane = threadIdx.x & 31;
    int h = lane >> 2;
    int q = lane & 3;

    int c = cnt[(size_t)node * HH + h];
    const float* wp = wcmp + ((size_t)node * HH + h) * 16;
    const int*   sp = scmp + ((size_t)node * HH + h) * 16;

    float4 acc = {0.f, 0.f, 0.f, 0.f};
    for (int j = 0; j < c; ++j) {
        float w = wp[j];
        int   s = sp[j];
        float4 v = *(const float4*)&hin[(size_t)s * DIMC + h * HDD + q * 4];
        acc.x += w * v.x; acc.y += w * v.y; acc.z += w * v.z; acc.w += w * v.w;
    }
    size_t o = (size_t)node * DIMC + h * HDD + q * 4;
    float4 f = *(const float4*)&fe[o];
    float4 r;
    r.x = (1.f - ALPHAC) * acc.x + ALPHAC * f.x;
    r.y = (1.f - ALPHAC) * acc.y + ALPHAC * f.y;
    r.z = (1.f - ALPHAC) * acc.z + ALPHAC * f.z;
    r.w = (1.f - ALPHAC) * acc.w + ALPHAC * f.w;
    *(float4*)&hout[o] = r;
}

// ---------------------------------------------------------------------------
extern "C" void kernel_launch(void* const* d_in, const int* in_sizes, int n_in,
                              void* d_out, int out_size)
{
    const float* feat   = (const float*)d_in[0];
    const float* W_head = (const float*)d_in[1];
    const float* W_tail = (const float*)d_in[2];
    const float* W_ent  = (const float*)d_in[3];
    const float* attn   = (const float*)d_in[4];
    const float* g1     = (const float*)d_in[5];
    const float* b1     = (const float*)d_in[6];
    const float* g2     = (const float*)d_in[7];
    const float* b2     = (const float*)d_in[8];
    const float* W_ff1  = (const float*)d_in[9];
    const float* b_ff1  = (const float*)d_in[10];
    const float* W_ff2  = (const float*)d_in[11];
    const float* b_ff2  = (const float*)d_in[12];
    const int*   src    = (const int*)d_in[13];
    float* out = (float*)d_out;

    int n = in_sizes[0] / DIMC;   // 50000
    if (n > NNODES) n = NNODES;

    float* scratch = nullptr;
    cudaGetSymbolAddress((void**)&scratch, g_scratch);
    const size_t SZ = (size_t)NNODES * DIMC;
    float* xln    = scratch + 0 * SZ;
    float* fh     = scratch + 1 * SZ;
    float* ft     = scratch + 2 * SZ;
    float* fe     = scratch + 3 * SZ;
    float* h0     = scratch + 4 * SZ;
    float* h1     = scratch + 5 * SZ;
    float* rst    = scratch + 6 * SZ;
    float* y      = scratch + 7 * SZ;
    float* hidden = scratch + 8 * SZ;          // 4*SZ
    float* wcmp   = scratch + 12 * SZ;         // N*8*16
    int*   scmp   = (int*)(scratch + 13 * SZ); // N*8*16
    int*   cnt    = (int*)(scratch + 14 * SZ); // N*8

    const int SMEM_BYTES = SMEM_FLOATS * 4;
    cudaFuncSetAttribute(k_gemm_tc, cudaFuncAttributeMaxDynamicSharedMemorySize, SMEM_BYTES);

    int lnGrid = (n + 7) / 8;
    int mTiles = (n + 127) / 128;
    int hopGrid = (n + 7) / 8;

    // x = LN(feat)
    k_ln<<<lnGrid, 256>>>(feat, nullptr, g1, b1, xln, nullptr, n);

    // fh/ft/fe projections (tensor cores, 3xTF32)
    dim3 gp(1, mTiles);
    k_gemm_tc<<<gp, 256, SMEM_BYTES>>>(xln, W_head, nullptr, nullptr, fh, n, 128, 128, 0);
    k_gemm_tc<<<gp, 256, SMEM_BYTES>>>(xln, W_tail, nullptr, nullptr, ft, n, 128, 128, 0);
    k_gemm_tc<<<gp, 256, SMEM_BYTES>>>(xln, W_ent,  nullptr, nullptr, fe, n, 128, 128, 0);

    // attention weights -> compact top-k lists
    k_attn<<<n, 128>>>(fh, ft, attn, src, wcmp, scmp, cnt, n);

    // 5 propagation hops (ping-pong)
    k_hop<<<hopGrid, 256>>>(fe, fe, wcmp, scmp, cnt, h0, n);
    k_hop<<<hopGrid, 256>>>(h0, fe, wcmp, scmp, cnt, h1, n);
    k_hop<<<hopGrid, 256>>>(h1, fe, wcmp, scmp, cnt, h0, n);
    k_hop<<<hopGrid, 256>>>(h0, fe, wcmp, scmp, cnt, h1, n);
    k_hop<<<hopGrid, 256>>>(h1, fe, wcmp, scmp, cnt, h0, n);

    // rst = h + feat; y = LN(rst)
    k_ln<<<lnGrid, 256>>>(h0, feat, g2, b2, y, rst, n);

    // hidden = relu(y @ W_ff1 + b_ff1)
    dim3 gf1(4, mTiles);
    k_gemm_tc<<<gf1, 256, SMEM_BYTES>>>(y, W_ff1, b_ff1, nullptr, hidden, n, 128, 512, 1);

    // out = hidden @ W_ff2 + b_ff2 + rst
    dim3 gf2(1, mTiles);
    k_gemm_tc<<<gf2, 256, SMEM_BYTES>>>(hidden, W_ff2, b_ff2, rst, out, n, 512, 128, 2);
}

// round 4
// speedup vs baseline: 1.6972x; 1.0076x over previous
#include <cuda_runtime.h>
#include <math.h>
#include <stdint.h>

#define NNODES 50000
#define DIMC   128
#define DD     16
#define HH     8
#define HDD    16
#define SLOPEC 0.2f
#define ALPHAC 0.1f
#define LNEPS  1e-5f
// ln(17)/16
#define SCORE_SCALE 0.17707583400351351f

// Scratch: 15*N*128 floats (~384MB)
__device__ float g_scratch[(size_t)NNODES * 1920];

// ---------------------------------------------------------------------------
// LayerNorm (optionally in+add, optionally store the pre-LN sum)
// ---------------------------------------------------------------------------
__global__ void k_ln(const float* __restrict__ in, const float* __restrict__ add,
                     const float* __restrict__ g, const float* __restrict__ b,
                     float* __restrict__ out, float* __restrict__ sum_out, int n)
{
    int row  = blockIdx.x * 8 + (threadIdx.x >> 5);
    int lane = threadIdx.x & 31;
    if (row >= n) return;

    float4 v = ((const float4*)in)[(size_t)row * 32 + lane];
    if (add) {
        float4 w = ((const float4*)add)[(size_t)row * 32 + lane];
        v.x += w.x; v.y += w.y; v.z += w.z; v.w += w.w;
    }
    if (sum_out) ((float4*)sum_out)[(size_t)row * 32 + lane] = v;

    float s = v.x + v.y + v.z + v.w;
    #pragma unroll
    for (int o = 16; o; o >>= 1) s += __shfl_xor_sync(0xffffffffu, s, o);
    float mu = s * (1.0f / 128.0f);

    float dx = v.x - mu, dy = v.y - mu, dz = v.z - mu, dw = v.w - mu;
    float vs = dx * dx + dy * dy + dz * dz + dw * dw;
    #pragma unroll
    for (int o = 16; o; o >>= 1) vs += __shfl_xor_sync(0xffffffffu, vs, o);
    float rs = rsqrtf(vs * (1.0f / 128.0f) + LNEPS);

    float4 gg = ((const float4*)g)[lane];
    float4 bb = ((const float4*)b)[lane];
    float4 o4;
    o4.x = dx * rs * gg.x + bb.x;
    o4.y = dy * rs * gg.y + bb.y;
    o4.z = dz * rs * gg.z + bb.z;
    o4.w = dw * rs * gg.w + bb.w;
    ((float4*)out)[(size_t)row * 32 + lane] = o4;
}

// ---------------------------------------------------------------------------
// Pipelined 3xTF32 tensor-core GEMM.
// Block 128x128, BK=32, double-buffered smem, register prefetch of next chunk.
// 8 warps (4x2), warp tile 32x64, 1 LDS per MMA.
// B selected per 128-col tile from {B0,B1,B2} (for fused projections).
// mode 0: plain  1: relu  2: + add[row,col]
// ---------------------------------------------------------------------------
#define BK     32
#define A_STR  36
#define B_STR  136
#define STG_FLOATS (2*128*A_STR + 2*BK*B_STR)   // 17920 floats / stage
#define GEMM_SMEM_BYTES (2*STG_FLOATS*4)        // 143360 B

__device__ __forceinline__ uint32_t f2tf32(float v) {
    uint32_t r;
    asm("cvt.rna.tf32.f32 %0, %1;" : "=r"(r) : "f"(v));
    return r;
}

__device__ __forceinline__ void split_sts(float4 v, float* hp, float* lp) {
    float4 hi, lo;
    uint32_t h;
    h = f2tf32(v.x); hi.x = __uint_as_float(h); lo.x = __uint_as_float(f2tf32(v.x - hi.x));
    h = f2tf32(v.y); hi.y = __uint_as_float(h); lo.y = __uint_as_float(f2tf32(v.y - hi.y));
    h = f2tf32(v.z); hi.z = __uint_as_float(h); lo.z = __uint_as_float(f2tf32(v.z - hi.z));
    h = f2tf32(v.w); hi.w = __uint_as_float(h); lo.w = __uint_as_float(f2tf32(v.w - hi.w));
    *(float4*)hp = hi;
    *(float4*)lp = lo;
}

__device__ __forceinline__ void mma8(float* c, const uint32_t* a, const uint32_t* b) {
    asm volatile("mma.sync.aligned.m16n8k8.row.col.f32.tf32.tf32.f32 "
        "{%0,%1,%2,%3}, {%4,%5,%6,%7}, {%8,%9}, {%0,%1,%2,%3};\n"
        : "+f"(c[0]), "+f"(c[1]), "+f"(c[2]), "+f"(c[3])
        : "r"(a[0]), "r"(a[1]), "r"(a[2]), "r"(a[3]), "r"(b[0]), "r"(b[1]));
}

__global__ void __launch_bounds__(256)
k_gemm_tc(const float* __restrict__ A,
          const float* __restrict__ B0, const float* __restrict__ B1,
          const float* __restrict__ B2,
          const float* __restrict__ bias, const float* __restrict__ add,
          float* __restrict__ C, int M, int K, int bNc, int cNc, int mode)
{
    extern __shared__ float sm[];

    int tid  = threadIdx.x;
    int warp = tid >> 5;
    int lane = tid & 31;
    int g    = lane >> 2;
    int tq   = lane & 3;
    int wr   = (warp >> 1) * 32;
    int wc   = (warp & 1) * 64;

    int row0 = blockIdx.y * 128;
    int c0   = blockIdx.x * 128;
    int bi   = c0 / bNc;
    const float* B = (bi == 0) ? B0 : ((bi == 1) ? B1 : B2);
    int bc0  = c0 - bi * bNc;

    // per-thread load coordinates (float4 granularity)
    int ar = tid >> 3;            // A row base; rows ar + s*32
    int ak = (tid & 7) << 2;      // A k offset 0..28
    int bk = tid >> 5;            // B k base; k = bk + s*8
    int bc = (tid & 31) << 2;     // B col offset 0..124

    float acc[2][8][4] = {};
    float4 pa[4], pb[4];

    int nch = K >> 5;

    // ---- prologue: load + split chunk 0 into stage 0 ----
    #pragma unroll
    for (int s = 0; s < 4; ++s) {
        int node = row0 + ar + s * 32;
        pa[s] = (node < M) ? *(const float4*)&A[(size_t)node * K + ak]
                           : make_float4(0.f, 0.f, 0.f, 0.f);
        pb[s] = *(const float4*)&B[(size_t)(bk + s * 8) * bNc + bc0 + bc];
    }
    {
        float* AsHi = sm;
        float* AsLo = AsHi + 128 * A_STR;
        float* BsHi = AsLo + 128 * A_STR;
        float* BsLo = BsHi + BK * B_STR;
        #pragma unroll
        for (int s = 0; s < 4; ++s) {
            int r = ar + s * 32;
            split_sts(pa[s], &AsHi[r * A_STR + ak], &AsLo[r * A_STR + ak]);
            int kk = bk + s * 8;
            split_sts(pb[s], &BsHi[kk * B_STR + bc], &BsLo[kk * B_STR + bc]);
        }
    }
    __syncthreads();

    for (int ch = 0; ch < nch; ++ch) {
        int cur = ch & 1;
        float* AsHi = sm + cur * STG_FLOATS;
        float* AsLo = AsHi + 128 * A_STR;
        float* BsHi = AsLo + 128 * A_STR;
        float* BsLo = BsHi + BK * B_STR;

        bool more = (ch + 1) < nch;
        if (more) {
            int k0 = (ch + 1) << 5;
            #pragma unroll
            for (int s = 0; s < 4; ++s) {
                int node = row0 + ar + s * 32;
                pa[s] = (node < M) ? *(const float4*)&A[(size_t)node * K + k0 + ak]
                                   : make_float4(0.f, 0.f, 0.f, 0.f);
                pb[s] = *(const float4*)&B[(size_t)(k0 + bk + s * 8) * bNc + bc0 + bc];
            }
        }

        // ---- MMA over current stage: 4 k-steps of 8 ----
        #pragma unroll
        for (int ks = 0; ks < 4; ++ks) {
            int k = ks * 8;
            uint32_t ahi[2][4], alo[2][4], bhi[8][2], blo[8][2];
            #pragma unroll
            for (int mf = 0; mf < 2; ++mf) {
                int r = wr + mf * 16 + g;
                ahi[mf][0] = __float_as_uint(AsHi[r * A_STR + k + tq]);
                ahi[mf][1] = __float_as_uint(AsHi[(r + 8) * A_STR + k + tq]);
                ahi[mf][2] = __float_as_uint(AsHi[r * A_STR + k + tq + 4]);
                ahi[mf][3] = __float_as_uint(AsHi[(r + 8) * A_STR + k + tq + 4]);
                alo[mf][0] = __float_as_uint(AsLo[r * A_STR + k + tq]);
                alo[mf][1] = __float_as_uint(AsLo[(r + 8) * A_STR + k + tq]);
                alo[mf][2] = __float_as_uint(AsLo[r * A_STR + k + tq + 4]);
                alo[mf][3] = __float_as_uint(AsLo[(r + 8) * A_STR + k + tq + 4]);
            }
            #pragma unroll
            for (int nf = 0; nf < 8; ++nf) {
                int c = wc + nf * 8 + g;
                bhi[nf][0] = __float_as_uint(BsHi[(k + tq) * B_STR + c]);
                bhi[nf][1] = __float_as_uint(BsHi[(k + tq + 4) * B_STR + c]);
                blo[nf][0] = __float_as_uint(BsLo[(k + tq) * B_STR + c]);
                blo[nf][1] = __float_as_uint(BsLo[(k + tq + 4) * B_STR + c]);
            }
            #pragma unroll
            for (int mf = 0; mf < 2; ++mf)
                #pragma unroll
                for (int nf = 0; nf < 8; ++nf) {
                    mma8(acc[mf][nf], ahi[mf], bhi[nf]);
                    mma8(acc[mf][nf], ahi[mf], blo[nf]);
                    mma8(acc[mf][nf], alo[mf], bhi[nf]);
                }
        }

        if (more) {
            float* nAsHi = sm + (cur ^ 1) * STG_FLOATS;
            float* nAsLo = nAsHi + 128 * A_STR;
            float* nBsHi = nAsLo + 128 * A_STR;
            float* nBsLo = nBsHi + BK * B_STR;
            #pragma unroll
            for (int s = 0; s < 4; ++s) {
                int r = ar + s * 32;
                split_sts(pa[s], &nAsHi[r * A_STR + ak], &nAsLo[r * A_STR + ak]);
                int kk = bk + s * 8;
                split_sts(pb[s], &nBsHi[kk * B_STR + bc], &nBsLo[kk * B_STR + bc]);
            }
            __syncthreads();
        }
    }

    // ---- epilogue ----
    #pragma unroll
    for (int mf = 0; mf < 2; ++mf) {
        #pragma unroll
        for (int nf = 0; nf < 8; ++nf) {
            int col = c0 + wc + nf * 8 + 2 * tq;
            float bx = 0.f, by = 0.f;
            if (bias) { bx = bias[col]; by = bias[col + 1]; }
            #pragma unroll
            for (int half = 0; half < 2; ++half) {
                int row = row0 + wr + mf * 16 + g + half * 8;
                if (row >= M) continue;
                float2 r;
                r.x = acc[mf][nf][half * 2 + 0] + bx;
                r.y = acc[mf][nf][half * 2 + 1] + by;
                size_t base = (size_t)row * cNc + col;
                if (mode == 1) {
                    r.x = fmaxf(r.x, 0.f); r.y = fmaxf(r.y, 0.f);
                } else if (mode == 2) {
                    float2 av = *(const float2*)&add[base];
                    r.x += av.x; r.y += av.y;
                }
                *(float2*)&C[base] = r;
            }
        }
    }
}

// ---------------------------------------------------------------------------
// Attention on packed fhte [N,384] (fh @ +0, ft @ +128):
// score -> softmax -> top-5 threshold -> compact normalized (w, src) lists.
// ---------------------------------------------------------------------------
#define FST 384

__global__ void k_attn(const float* __restrict__ fhte, const float* __restrict__ attn,
                       const int* __restrict__ src,
                       float* __restrict__ wcmp, int* __restrict__ scmp,
                       int* __restrict__ cnt, int n)
{
    int node = blockIdx.x;
    int tid  = threadIdx.x;
    __shared__ __align__(16) float fts[DIMC];
    __shared__ __align__(16) float ats[DIMC];
    __shared__ int   srcs[DD];
    __shared__ float sc[DD][HH];

    fts[tid] = fhte[(size_t)node * FST + 128 + tid];
    ats[tid] = attn[tid];
    if (tid < DD) srcs[tid] = src[(size_t)node * DD + tid];
    __syncthreads();

    int d = tid >> 3;
    int h = tid & 7;
    const float4* fr = (const float4*)(fhte + (size_t)srcs[d] * FST + h * HDD);
    const float4* tr = (const float4*)(fts + h * HDD);
    const float4* ar = (const float4*)(ats + h * HDD);
    float s = 0.f;
    #pragma unroll
    for (int f = 0; f < 4; ++f) {
        float4 fv = fr[f], tv = tr[f], av = ar[f];
        float e;
        e = fv.x + tv.x; e = (e >= 0.f) ? e : SLOPEC * e; s += e * av.x;
        e = fv.y + tv.y; e = (e >= 0.f) ? e : SLOPEC * e; s += e * av.y;
        e = fv.z + tv.z; e = (e >= 0.f) ? e : SLOPEC * e; s += e * av.z;
        e = fv.w + tv.w; e = (e >= 0.f) ? e : SLOPEC * e; s += e * av.w;
    }
    sc[d][h] = s * SCORE_SCALE;
    __syncthreads();

    if (tid < HH) {
        int hh = tid;
        float a[DD];
        float m = -1e30f;
        #pragma unroll
        for (int dd = 0; dd < DD; ++dd) { a[dd] = sc[dd][hh]; m = fmaxf(m, a[dd]); }
        float sum = 0.f;
        #pragma unroll
        for (int dd = 0; dd < DD; ++dd) { a[dd] = expf(a[dd] - m); sum += a[dd]; }
        float inv = 1.f / sum;
        #pragma unroll
        for (int dd = 0; dd < DD; ++dd) a[dd] *= inv;

        // 5th-largest (counting duplicates) via 5-pass max removal
        float t[DD];
        #pragma unroll
        for (int dd = 0; dd < DD; ++dd) t[dd] = a[dd];
        float thr = 0.f;
        #pragma unroll
        for (int it = 0; it < 5; ++it) {
            float mx = -1.f; int mi = 0;
            #pragma unroll
            for (int dd = 0; dd < DD; ++dd)
                if (t[dd] > mx) { mx = t[dd]; mi = dd; }
            thr = mx;
            t[mi] = -1.f;
        }
        float ts = 0.f;
        #pragma unroll
        for (int dd = 0; dd < DD; ++dd)
            if (a[dd] >= thr) ts += a[dd];
        float itn = 1.f / ts;

        size_t base = ((size_t)node * HH + hh) * 16;
        int c = 0;
        #pragma unroll
        for (int dd = 0; dd < DD; ++dd) {
            if (a[dd] >= thr) {
                wcmp[base + c] = a[dd] * itn;
                scmp[base + c] = srcs[dd];
                ++c;
            }
        }
        cnt[(size_t)node * HH + hh] = c;
    }
}

// ---------------------------------------------------------------------------
// One propagation hop using compact lists. One warp per node.
// lane -> (h = lane/4, q = lane%4): float4 over 16 feats of head h.
// hin has row stride instr; fe (already offset) has row stride festr.
// ---------------------------------------------------------------------------
__global__ void k_hop(const float* __restrict__ hin, int instr,
                      const float* __restrict__ fe, int festr,
                      const float* __restrict__ wcmp, const int* __restrict__ scmp,
                      const int* __restrict__ cnt, float* __restrict__ hout, int n)
{
    int node = blockIdx.x * 8 + (threadIdx.x >> 5);
    if (node >= n) return;
    int lane = threadIdx.x & 31;
    int h = lane >> 2;
    int q = lane & 3;

    int c = cnt[(size_t)node * HH + h];
    const float* wp = wcmp + ((size_t)node * HH + h) * 16;
    const int*   sp = scmp + ((size_t)node * HH + h) * 16;

    float4 acc = {0.f, 0.f, 0.f, 0.f};
    for (int j = 0; j < c; ++j) {
        float w = wp[j];
        int   s = sp[j];
        float4 v = *(const float4*)&hin[(size_t)s * instr + h * HDD + q * 4];
        acc.x += w * v.x; acc.y += w * v.y; acc.z += w * v.z; acc.w += w * v.w;
    }
    float4 f = *(const float4*)&fe[(size_t)node * festr + h * HDD + q * 4];
    float4 r;
    r.x = (1.f - ALPHAC) * acc.x + ALPHAC * f.x;
    r.y = (1.f - ALPHAC) * acc.y + ALPHAC * f.y;
    r.z = (1.f - ALPHAC) * acc.z + ALPHAC * f.z;
    r.w = (1.f - ALPHAC) * acc.w + ALPHAC * f.w;
    *(float4*)&hout[(size_t)node * DIMC + h * HDD + q * 4] = r;
}

// ---------------------------------------------------------------------------
extern "C" void kernel_launch(void* const* d_in, const int* in_sizes, int n_in,
                              void* d_out, int out_size)
{
    const float* feat   = (const float*)d_in[0];
    const float* W_head = (const float*)d_in[1];
    const float* W_tail = (const float*)d_in[2];
    const float* W_ent  = (const float*)d_in[3];
    const float* attn   = (const float*)d_in[4];
    const float* g1     = (const float*)d_in[5];
    const float* b1     = (const float*)d_in[6];
    const float* g2     = (const float*)d_in[7];
    const float* b2     = (const float*)d_in[8];
    const float* W_ff1  = (const float*)d_in[9];
    const float* b_ff1  = (const float*)d_in[10];
    const float* W_ff2  = (const float*)d_in[11];
    const float* b_ff2  = (const float*)d_in[12];
    const int*   src    = (const int*)d_in[13];
    float* out = (float*)d_out;

    int n = in_sizes[0] / DIMC;   // 50000
    if (n > NNODES) n = NNODES;

    float* scratch = nullptr;
    cudaGetSymbolAddress((void**)&scratch, g_scratch);
    const size_t SZ = (size_t)NNODES * DIMC;
    float* xln    = scratch + 0 * SZ;
    float* fhte   = scratch + 1 * SZ;          // N*384: fh|ft|fe packed
    float* h0     = scratch + 4 * SZ;
    float* h1     = scratch + 5 * SZ;
    float* rst    = scratch + 6 * SZ;
    float* y      = scratch + 7 * SZ;
    float* hidden = scratch + 8 * SZ;          // N*512
    float* wcmp   = scratch + 12 * SZ;         // N*8*16
    int*   scmp   = (int*)(scratch + 13 * SZ); // N*8*16
    int*   cnt    = (int*)(scratch + 14 * SZ); // N*8
    float* fe     = fhte + 256;                // column offset within packed rows

    cudaFuncSetAttribute(k_gemm_tc, cudaFuncAttributeMaxDynamicSharedMemorySize,
                         GEMM_SMEM_BYTES);

    int lnGrid  = (n + 7) / 8;
    int mTiles  = (n + 127) / 128;
    int hopGrid = (n + 7) / 8;

    // x = LN(feat)
    k_ln<<<lnGrid, 256>>>(feat, nullptr, g1, b1, xln, nullptr, n);

    // fused fh|ft|fe projection: [N,128] @ {Wh|Wt|We} -> [N,384]
    dim3 gp(3, mTiles);
    k_gemm_tc<<<gp, 256, GEMM_SMEM_BYTES>>>(xln, W_head, W_tail, W_ent,
                                            nullptr, nullptr, fhte,
                                            n, 128, 128, 384, 0);

    // attention -> compact top-k lists
    k_attn<<<n, 128>>>(fhte, attn, src, wcmp, scmp, cnt, n);

    // 5 propagation hops (first reads fe in packed layout, rest ping-pong)
    k_hop<<<hopGrid, 256>>>(fe, FST, fe, FST, wcmp, scmp, cnt, h0, n);
    k_hop<<<hopGrid, 256>>>(h0, DIMC, fe, FST, wcmp, scmp, cnt, h1, n);
    k_hop<<<hopGrid, 256>>>(h1, DIMC, fe, FST, wcmp, scmp, cnt, h0, n);
    k_hop<<<hopGrid, 256>>>(h0, DIMC, fe, FST, wcmp, scmp, cnt, h1, n);
    k_hop<<<hopGrid, 256>>>(h1, DIMC, fe, FST, wcmp, scmp, cnt, h0, n);

    // rst = h + feat; y = LN(rst)
    k_ln<<<lnGrid, 256>>>(h0, feat, g2, b2, y, rst, n);

    // hidden = relu(y @ W_ff1 + b_ff1)
    dim3 gf1(4, mTiles);
    k_gemm_tc<<<gf1, 256, GEMM_SMEM_BYTES>>>(y, W_ff1, W_ff1, W_ff1,
                                             b_ff1, nullptr, hidden,
                                             n, 128, 512, 512, 1);

    // out = hidden @ W_ff2 + b_ff2 + rst
    dim3 gf2(1, mTiles);
    k_gemm_tc<<<gf2, 256, GEMM_SMEM_BYTES>>>(hidden, W_ff2, W_ff2, W_ff2,
                                             b_ff2, rst, out,
                                             n, 512, 128, 128, 2);
}

// round 5
// speedup vs baseline: 2.1739x; 1.2809x over previous
#include <cuda_runtime.h>
#include <cuda_bf16.h>
#include <math.h>
#include <stdint.h>

#define NNODES 50000
#define DIMC   128
#define DD     16
#define HH     8
#define HDD    16
#define SLOPEC 0.2f
#define ALPHAC 0.1f
#define LNEPS  1e-5f
// ln(17)/16
#define SCORE_SCALE 0.17707583400351351f

// Scratch: 15*N*128 floats (~384MB)
__device__ float g_scratch[(size_t)NNODES * 1920];

// ---------------------------------------------------------------------------
// LayerNorm (optionally in+add, optionally store the pre-LN sum)
// ---------------------------------------------------------------------------
__global__ void k_ln(const float* __restrict__ in, const float* __restrict__ add,
                     const float* __restrict__ g, const float* __restrict__ b,
                     float* __restrict__ out, float* __restrict__ sum_out, int n)
{
    int row  = blockIdx.x * 8 + (threadIdx.x >> 5);
    int lane = threadIdx.x & 31;
    if (row >= n) return;

    float4 v = ((const float4*)in)[(size_t)row * 32 + lane];
    if (add) {
        float4 w = ((const float4*)add)[(size_t)row * 32 + lane];
        v.x += w.x; v.y += w.y; v.z += w.z; v.w += w.w;
    }
    if (sum_out) ((float4*)sum_out)[(size_t)row * 32 + lane] = v;

    float s = v.x + v.y + v.z + v.w;
    #pragma unroll
    for (int o = 16; o; o >>= 1) s += __shfl_xor_sync(0xffffffffu, s, o);
    float mu = s * (1.0f / 128.0f);

    float dx = v.x - mu, dy = v.y - mu, dz = v.z - mu, dw = v.w - mu;
    float vs = dx * dx + dy * dy + dz * dz + dw * dw;
    #pragma unroll
    for (int o = 16; o; o >>= 1) vs += __shfl_xor_sync(0xffffffffu, vs, o);
    float rs = rsqrtf(vs * (1.0f / 128.0f) + LNEPS);

    float4 gg = ((const float4*)g)[lane];
    float4 bb = ((const float4*)b)[lane];
    float4 o4;
    o4.x = dx * rs * gg.x + bb.x;
    o4.y = dy * rs * gg.y + bb.y;
    o4.z = dz * rs * gg.z + bb.z;
    o4.w = dw * rs * gg.w + bb.w;
    ((float4*)out)[(size_t)row * 32 + lane] = o4;
}

// ---------------------------------------------------------------------------
// bf16x3 tensor-core GEMM (m16n8k16): C = epi(A @ B + bias)
// A,B split A=ahi+alo (bf16); C += AhiBhi + AhiBlo + AloBhi (fp32 accum).
// Block 128x128, BK=32, double-buffered smem (packed bf16x2), 8 warps (4x2),
// warp tile 32x64. 2 CTAs/SM.
// B selected per 128-col tile from {B0,B1,B2}; tile bi==2 optionally writes C2.
// mode 0: plain  1: relu  2: + add[row,col]
// ---------------------------------------------------------------------------
#define BK      32
#define A_STR2  20     // uint32 stride per A row (16 kp + pad)
#define B_STR2  136    // uint32 stride per B kp row (128 cols + pad)
#define STG_U32 (2*128*A_STR2 + 2*(BK/2)*B_STR2)   // 9472 u32 per stage
#define GEMM_SMEM_BYTES (2*STG_U32*4)              // 75776 B

__device__ __forceinline__ void bfsplit(float v0, float v1, uint32_t& hi, uint32_t& lo) {
    __nv_bfloat16 h0 = __float2bfloat16(v0);
    __nv_bfloat16 h1 = __float2bfloat16(v1);
    float r0 = v0 - __bfloat162float(h0);
    float r1 = v1 - __bfloat162float(h1);
    __nv_bfloat16 l0 = __float2bfloat16(r0);
    __nv_bfloat16 l1 = __float2bfloat16(r1);
    hi = ((uint32_t)__bfloat16_as_ushort(h1) << 16) | (uint32_t)__bfloat16_as_ushort(h0);
    lo = ((uint32_t)__bfloat16_as_ushort(l1) << 16) | (uint32_t)__bfloat16_as_ushort(l0);
}

__device__ __forceinline__ void mma16(float* c, const uint32_t* a, const uint32_t* b) {
    asm volatile("mma.sync.aligned.m16n8k16.row.col.f32.bf16.bf16.f32 "
        "{%0,%1,%2,%3}, {%4,%5,%6,%7}, {%8,%9}, {%0,%1,%2,%3};\n"
        : "+f"(c[0]), "+f"(c[1]), "+f"(c[2]), "+f"(c[3])
        : "r"(a[0]), "r"(a[1]), "r"(a[2]), "r"(a[3]), "r"(b[0]), "r"(b[1]));
}

__global__ void __launch_bounds__(256, 2)
k_gemm_tc(const float* __restrict__ A,
          const float* __restrict__ B0, const float* __restrict__ B1,
          const float* __restrict__ B2,
          const float* __restrict__ bias, const float* __restrict__ add,
          float* __restrict__ C, float* __restrict__ C2,
          int M, int K, int bNc, int cNc, int mode)
{
    extern __shared__ uint32_t smu[];

    int tid  = threadIdx.x;
    int warp = tid >> 5;
    int lane = tid & 31;
    int g    = lane >> 2;
    int tq   = lane & 3;
    int wr   = (warp >> 1) * 32;
    int wc   = (warp & 1) * 64;

    int row0 = blockIdx.y * 128;
    int c0   = blockIdx.x * 128;
    int bi   = c0 / bNc;
    const float* B = (bi == 0) ? B0 : ((bi == 1) ? B1 : B2);
    int bc0  = c0 - bi * bNc;

    // loader coords
    int ar = tid >> 3;            // A row base; rows ar + s*32
    int ak = (tid & 7) << 2;      // A k offset 0..28 (mult of 4)
    // B: slots tid + s*256, kp = slot>>5, c4 = (slot&31)*4

    float acc[2][8][4] = {};
    float4 pa[4];
    float4 pb0[2], pb1[2];

    int nch = K >> 5;

    // ---- prologue: load chunk 0 ----
    #pragma unroll
    for (int s = 0; s < 4; ++s) {
        int node = row0 + ar + s * 32;
        pa[s] = (node < M) ? *(const float4*)&A[(size_t)node * K + ak]
                           : make_float4(0.f, 0.f, 0.f, 0.f);
    }
    #pragma unroll
    for (int s = 0; s < 2; ++s) {
        int slot = tid + s * 256;
        int kp = slot >> 5;
        int cc = (slot & 31) << 2;
        pb0[s] = *(const float4*)&B[(size_t)(2 * kp)     * bNc + bc0 + cc];
        pb1[s] = *(const float4*)&B[(size_t)(2 * kp + 1) * bNc + bc0 + cc];
    }
    // ---- split + STS into stage 0 ----
    {
        uint32_t* AsHi = smu;
        uint32_t* AsLo = AsHi + 128 * A_STR2;
        uint32_t* BsHi = AsLo + 128 * A_STR2;
        uint32_t* BsLo = BsHi + (BK/2) * B_STR2;
        #pragma unroll
        for (int s = 0; s < 4; ++s) {
            int r = ar + s * 32;
            uint32_t h0, l0, h1, l1;
            bfsplit(pa[s].x, pa[s].y, h0, l0);
            bfsplit(pa[s].z, pa[s].w, h1, l1);
            *(uint2*)&AsHi[r * A_STR2 + (ak >> 1)] = make_uint2(h0, h1);
            *(uint2*)&AsLo[r * A_STR2 + (ak >> 1)] = make_uint2(l0, l1);
        }
        #pragma unroll
        for (int s = 0; s < 2; ++s) {
            int slot = tid + s * 256;
            int kp = slot >> 5;
            int cc = (slot & 31) << 2;
            uint32_t h[4], l[4];
            bfsplit(pb0[s].x, pb1[s].x, h[0], l[0]);
            bfsplit(pb0[s].y, pb1[s].y, h[1], l[1]);
            bfsplit(pb0[s].z, pb1[s].z, h[2], l[2]);
            bfsplit(pb0[s].w, pb1[s].w, h[3], l[3]);
            *(uint4*)&BsHi[kp * B_STR2 + cc] = make_uint4(h[0], h[1], h[2], h[3]);
            *(uint4*)&BsLo[kp * B_STR2 + cc] = make_uint4(l[0], l[1], l[2], l[3]);
        }
    }
    __syncthreads();

    for (int ch = 0; ch < nch; ++ch) {
        int cur = ch & 1;
        uint32_t* AsHi = smu + cur * STG_U32;
        uint32_t* AsLo = AsHi + 128 * A_STR2;
        uint32_t* BsHi = AsLo + 128 * A_STR2;
        uint32_t* BsLo = BsHi + (BK/2) * B_STR2;

        bool more = (ch + 1) < nch;
        if (more) {
            int k0 = (ch + 1) << 5;
            #pragma unroll
            for (int s = 0; s < 4; ++s) {
                int node = row0 + ar + s * 32;
                pa[s] = (node < M) ? *(const float4*)&A[(size_t)node * K + k0 + ak]
                                   : make_float4(0.f, 0.f, 0.f, 0.f);
            }
            #pragma unroll
            for (int s = 0; s < 2; ++s) {
                int slot = tid + s * 256;
                int kp = slot >> 5;
                int cc = (slot & 31) << 2;
                pb0[s] = *(const float4*)&B[(size_t)(k0 + 2 * kp)     * bNc + bc0 + cc];
                pb1[s] = *(const float4*)&B[(size_t)(k0 + 2 * kp + 1) * bNc + bc0 + cc];
            }
        }

        // ---- MMA over current stage: 2 k16-steps ----
        #pragma unroll
        for (int ks = 0; ks < 2; ++ks) {
            int kb = ks * 8;     // kp base
            uint32_t ahi[2][4], alo[2][4];
            #pragma unroll
            for (int mf = 0; mf < 2; ++mf) {
                int r = wr + mf * 16 + g;
                ahi[mf][0] = AsHi[r * A_STR2 + kb + tq];
                ahi[mf][1] = AsHi[(r + 8) * A_STR2 + kb + tq];
                ahi[mf][2] = AsHi[r * A_STR2 + kb + tq + 4];
                ahi[mf][3] = AsHi[(r + 8) * A_STR2 + kb + tq + 4];
                alo[mf][0] = AsLo[r * A_STR2 + kb + tq];
                alo[mf][1] = AsLo[(r + 8) * A_STR2 + kb + tq];
                alo[mf][2] = AsLo[r * A_STR2 + kb + tq + 4];
                alo[mf][3] = AsLo[(r + 8) * A_STR2 + kb + tq + 4];
            }
            #pragma unroll
            for (int nf = 0; nf < 8; ++nf) {
                int c = wc + nf * 8 + g;
                uint32_t bhi[2], blo[2];
                bhi[0] = BsHi[(kb + tq) * B_STR2 + c];
                bhi[1] = BsHi[(kb + tq + 4) * B_STR2 + c];
                blo[0] = BsLo[(kb + tq) * B_STR2 + c];
                blo[1] = BsLo[(kb + tq + 4) * B_STR2 + c];
                #pragma unroll
                for (int mf = 0; mf < 2; ++mf) {
                    mma16(acc[mf][nf], ahi[mf], bhi);
                    mma16(acc[mf][nf], ahi[mf], blo);
                    mma16(acc[mf][nf], alo[mf], bhi);
                }
            }
        }

        if (more) {
            uint32_t* nAsHi = smu + (cur ^ 1) * STG_U32;
            uint32_t* nAsLo = nAsHi + 128 * A_STR2;
            uint32_t* nBsHi = nAsLo + 128 * A_STR2;
            uint32_t* nBsLo = nBsHi + (BK/2) * B_STR2;
            #pragma unroll
            for (int s = 0; s < 4; ++s) {
                int r = ar + s * 32;
                uint32_t h0, l0, h1, l1;
                bfsplit(pa[s].x, pa[s].y, h0, l0);
                bfsplit(pa[s].z, pa[s].w, h1, l1);
                *(uint2*)&nAsHi[r * A_STR2 + (ak >> 1)] = make_uint2(h0, h1);
                *(uint2*)&nAsLo[r * A_STR2 + (ak >> 1)] = make_uint2(l0, l1);
            }
            #pragma unroll
            for (int s = 0; s < 2; ++s) {
                int slot = tid + s * 256;
                int kp = slot >> 5;
                int cc = (slot & 31) << 2;
                uint32_t h[4], l[4];
                bfsplit(pb0[s].x, pb1[s].x, h[0], l[0]);
                bfsplit(pb0[s].y, pb1[s].y, h[1], l[1]);
                bfsplit(pb0[s].z, pb1[s].z, h[2], l[2]);
                bfsplit(pb0[s].w, pb1[s].w, h[3], l[3]);
                *(uint4*)&nBsHi[kp * B_STR2 + cc] = make_uint4(h[0], h[1], h[2], h[3]);
                *(uint4*)&nBsLo[kp * B_STR2 + cc] = make_uint4(l[0], l[1], l[2], l[3]);
            }
            __syncthreads();
        }
    }

    // ---- epilogue (tile bi==2 optionally redirected to dense C2) ----
    float* Co = C;
    int ostr  = cNc;
    int ocol0 = c0;
    if (C2 && bi == 2) { Co = C2; ostr = 128; ocol0 = bc0; }

    #pragma unroll
    for (int mf = 0; mf < 2; ++mf) {
        #pragma unroll
        for (int nf = 0; nf < 8; ++nf) {
            int col = ocol0 + wc + nf * 8 + 2 * tq;
            float bx = 0.f, by = 0.f;
            if (bias) { bx = bias[col]; by = bias[col + 1]; }
            #pragma unroll
            for (int half = 0; half < 2; ++half) {
                int row = row0 + wr + mf * 16 + g + half * 8;
                if (row >= M) continue;
                float2 r;
                r.x = acc[mf][nf][half * 2 + 0] + bx;
                r.y = acc[mf][nf][half * 2 + 1] + by;
                size_t base = (size_t)row * ostr + col;
                if (mode == 1) {
                    r.x = fmaxf(r.x, 0.f); r.y = fmaxf(r.y, 0.f);
                } else if (mode == 2) {
                    float2 av = *(const float2*)&add[base];
                    r.x += av.x; r.y += av.y;
                }
                *(float2*)&Co[base] = r;
            }
        }
    }
}

// ---------------------------------------------------------------------------
// Attention on packed fht [N,256] (fh @ +0, ft @ +128):
// score -> softmax -> top-5 threshold -> compact (w, src) pair lists.
// ---------------------------------------------------------------------------
#define FST 256

__global__ void k_attn(const float* __restrict__ fht, const float* __restrict__ attn,
                       const int* __restrict__ src,
                       float2* __restrict__ ws, int* __restrict__ cnt, int n)
{
    int node = blockIdx.x;
    int tid  = threadIdx.x;
    __shared__ __align__(16) float fts[DIMC];
    __shared__ __align__(16) float ats[DIMC];
    __shared__ int   srcs[DD];
    __shared__ float sc[DD][HH];

    fts[tid] = fht[(size_t)node * FST + 128 + tid];
    ats[tid] = attn[tid];
    if (tid < DD) srcs[tid] = src[(size_t)node * DD + tid];
    __syncthreads();

    int d = tid >> 3;
    int h = tid & 7;
    const float4* fr = (const float4*)(fht + (size_t)srcs[d] * FST + h * HDD);
    const float4* tr = (const float4*)(fts + h * HDD);
    const float4* ar = (const float4*)(ats + h * HDD);
    float s = 0.f;
    #pragma unroll
    for (int f = 0; f < 4; ++f) {
        float4 fv = fr[f], tv = tr[f], av = ar[f];
        float e;
        e = fv.x + tv.x; e = (e >= 0.f) ? e : SLOPEC * e; s += e * av.x;
        e = fv.y + tv.y; e = (e >= 0.f) ? e : SLOPEC * e; s += e * av.y;
        e = fv.z + tv.z; e = (e >= 0.f) ? e : SLOPEC * e; s += e * av.z;
        e = fv.w + tv.w; e = (e >= 0.f) ? e : SLOPEC * e; s += e * av.w;
    }
    sc[d][h] = s * SCORE_SCALE;
    __syncthreads();

    if (tid < HH) {
        int hh = tid;
        float a[DD];
        float m = -1e30f;
        #pragma unroll
        for (int dd = 0; dd < DD; ++dd) { a[dd] = sc[dd][hh]; m = fmaxf(m, a[dd]); }
        float sum = 0.f;
        #pragma unroll
        for (int dd = 0; dd < DD; ++dd) { a[dd] = expf(a[dd] - m); sum += a[dd]; }
        float inv = 1.f / sum;
        #pragma unroll
        for (int dd = 0; dd < DD; ++dd) a[dd] *= inv;

        // 5th-largest (counting duplicates) via 5-pass max removal
        float t[DD];
        #pragma unroll
        for (int dd = 0; dd < DD; ++dd) t[dd] = a[dd];
        float thr = 0.f;
        #pragma unroll
        for (int it = 0; it < 5; ++it) {
            float mx = -1.f; int mi = 0;
            #pragma unroll
            for (int dd = 0; dd < DD; ++dd)
                if (t[dd] > mx) { mx = t[dd]; mi = dd; }
            thr = mx;
            t[mi] = -1.f;
        }
        float ts = 0.f;
        #pragma unroll
        for (int dd = 0; dd < DD; ++dd)
            if (a[dd] >= thr) ts += a[dd];
        float itn = 1.f / ts;

        size_t base = ((size_t)node * HH + hh) * 16;
        int c = 0;
        #pragma unroll
        for (int dd = 0; dd < DD; ++dd) {
            if (a[dd] >= thr) {
                ws[base + c] = make_float2(a[dd] * itn, __int_as_float(srcs[dd]));
                ++c;
            }
        }
        cnt[(size_t)node * HH + hh] = c;
    }
}

// ---------------------------------------------------------------------------
// One propagation hop using compact (w,src) lists. One warp per node.
// lane -> (h = lane/4, q = lane%4): float4 over 16 feats of head h.
// ---------------------------------------------------------------------------
__global__ void k_hop(const float* __restrict__ hin, const float* __restrict__ fe,
                      const float2* __restrict__ ws, const int* __restrict__ cnt,
                      float* __restrict__ hout, int n)
{
    int node = blockIdx.x * 8 + (threadIdx.x >> 5);
    if (node >= n) return;
    int lane = threadIdx.x & 31;
    int h = lane >> 2;
    int q = lane & 3;

    int c = cnt[(size_t)node * HH + h];
    const float2* wp = ws + ((size_t)node * HH + h) * 16;

    float4 acc = {0.f, 0.f, 0.f, 0.f};
    for (int j = 0; j < c; ++j) {
        float2 e = wp[j];
        float w = e.x;
        int   s = __float_as_int(e.y);
        float4 v = *(const float4*)&hin[(size_t)s * DIMC + h * HDD + q * 4];
        acc.x += w * v.x; acc.y += w * v.y; acc.z += w * v.z; acc.w += w * v.w;
    }
    size_t o = (size_t)node * DIMC + h * HDD + q * 4;
    float4 f = *(const float4*)&fe[o];
    float4 r;
    r.x = (1.f - ALPHAC) * acc.x + ALPHAC * f.x;
    r.y = (1.f - ALPHAC) * acc.y + ALPHAC * f.y;
    r.z = (1.f - ALPHAC) * acc.z + ALPHAC * f.z;
    r.w = (1.f - ALPHAC) * acc.w + ALPHAC * f.w;
    *(float4*)&hout[o] = r;
}

// ---------------------------------------------------------------------------
extern "C" void kernel_launch(void* const* d_in, const int* in_sizes, int n_in,
                              void* d_out, int out_size)
{
    const float* feat   = (const float*)d_in[0];
    const float* W_head = (const float*)d_in[1];
    const float* W_tail = (const float*)d_in[2];
    const float* W_ent  = (const float*)d_in[3];
    const float* attn   = (const float*)d_in[4];
    const float* g1     = (const float*)d_in[5];
    const float* b1     = (const float*)d_in[6];
    const float* g2     = (const float*)d_in[7];
    const float* b2     = (const float*)d_in[8];
    const float* W_ff1  = (const float*)d_in[9];
    const float* b_ff1  = (const float*)d_in[10];
    const float* W_ff2  = (const float*)d_in[11];
    const float* b_ff2  = (const float*)d_in[12];
    const int*   src    = (const int*)d_in[13];
    float* out = (float*)d_out;

    int n = in_sizes[0] / DIMC;   // 50000
    if (n > NNODES) n = NNODES;

    float* scratch = nullptr;
    cudaGetSymbolAddress((void**)&scratch, g_scratch);
    const size_t SZ = (size_t)NNODES * DIMC;
    float*  xln    = scratch + 0 * SZ;
    float*  fht    = scratch + 1 * SZ;          // N*256: fh|ft packed
    float*  fe     = scratch + 3 * SZ;          // N*128 dense
    float*  h0     = scratch + 4 * SZ;
    float*  h1     = scratch + 5 * SZ;
    float*  rst    = scratch + 6 * SZ;
    float*  y      = scratch + 7 * SZ;
    float*  hidden = scratch + 8 * SZ;          // N*512
    float2* ws     = (float2*)(scratch + 12 * SZ); // N*8*16 pairs
    int*    cnt    = (int*)(scratch + 14 * SZ);    // N*8

    cudaFuncSetAttribute(k_gemm_tc, cudaFuncAttributeMaxDynamicSharedMemorySize,
                         GEMM_SMEM_BYTES);

    int lnGrid  = (n + 7) / 8;
    int mTiles  = (n + 127) / 128;
    int hopGrid = (n + 7) / 8;

    // x = LN(feat)
    k_ln<<<lnGrid, 256>>>(feat, nullptr, g1, b1, xln, nullptr, n);

    // fused projection: tiles 0,1 -> fht [N,256]; tile 2 -> fe dense [N,128]
    dim3 gp(3, mTiles);
    k_gemm_tc<<<gp, 256, GEMM_SMEM_BYTES>>>(xln, W_head, W_tail, W_ent,
                                            nullptr, nullptr, fht, fe,
                                            n, 128, 128, 256, 0);

    // attention -> compact top-k pair lists
    k_attn<<<n, 128>>>(fht, attn, src, ws, cnt, n);

    // 5 propagation hops (ping-pong)
    k_hop<<<hopGrid, 256>>>(fe, fe, ws, cnt, h0, n);
    k_hop<<<hopGrid, 256>>>(h0, fe, ws, cnt, h1, n);
    k_hop<<<hopGrid, 256>>>(h1, fe, ws, cnt, h0, n);
    k_hop<<<hopGrid, 256>>>(h0, fe, ws, cnt, h1, n);
    k_hop<<<hopGrid, 256>>>(h1, fe, ws, cnt, h0, n);

    // rst = h + feat; y = LN(rst)
    k_ln<<<lnGrid, 256>>>(h0, feat, g2, b2, y, rst, n);

    // hidden = relu(y @ W_ff1 + b_ff1)
    dim3 gf1(4, mTiles);
    k_gemm_tc<<<gf1, 256, GEMM_SMEM_BYTES>>>(y, W_ff1, W_ff1, W_ff1,
                                             b_ff1, nullptr, hidden, nullptr,
                                             n, 128, 512, 512, 1);

    // out = hidden @ W_ff2 + b_ff2 + rst
    dim3 gf2(1, mTiles);
    k_gemm_tc<<<gf2, 256, GEMM_SMEM_BYTES>>>(hidden, W_ff2, W_ff2, W_ff2,
                                             b_ff2, rst, out, nullptr,
                                             n, 512, 128, 128, 2);
}